// round 3
// baseline (speedup 1.0000x reference)
#include <cuda_runtime.h>
#include <math.h>

#define T_TOK 1024
#define HDIM  2048
#define NEXP  16
#define KSEL  4
#define IDIM  1408
#define ISDIM 2816

// ---------------- scratch (static device globals; no allocation APIs) ----------------
__device__ int   g_counts[NEXP];
__device__ int   g_tokens[NEXP * T_TOK];
__device__ float g_wts[NEXP * T_TOK];
__device__ float g_act[(size_t)NEXP * T_TOK * IDIM];   // routed SwiGLU activations, grouped by expert (~92 MB)
__device__ float g_acts[(size_t)T_TOK * ISDIM];        // shared-expert SwiGLU activations (~11.5 MB)

// ---------------- kernel 0: reset per-expert counters ----------------
__global__ void zero_counts_kernel() {
    if (threadIdx.x < NEXP) g_counts[threadIdx.x] = 0;
}

// ---------------- kernel 1: router (softmax -> top-4 -> renorm -> scatter) ----------------
__global__ void gate_kernel(const float* __restrict__ x, const float* __restrict__ gw) {
    int t = blockIdx.x;
    __shared__ float xs[HDIM];
    __shared__ float logits[NEXP];
    const float* xrow = x + (size_t)t * HDIM;
    for (int i = threadIdx.x; i < HDIM; i += blockDim.x) xs[i] = xrow[i];
    __syncthreads();

    int warp = threadIdx.x >> 5, lane = threadIdx.x & 31;
    for (int e = warp; e < NEXP; e += 8) {
        const float* grow = gw + (size_t)e * HDIM;
        float s = 0.f;
        for (int h = lane; h < HDIM; h += 32) s += xs[h] * grow[h];
        #pragma unroll
        for (int o = 16; o > 0; o >>= 1) s += __shfl_xor_sync(0xffffffffu, s, o);
        if (lane == 0) logits[e] = s;
    }
    __syncthreads();

    if (threadIdx.x == 0) {
        float mx = -1e30f;
        for (int e = 0; e < NEXP; e++) mx = fmaxf(mx, logits[e]);
        float sc[NEXP]; float se = 0.f;
        for (int e = 0; e < NEXP; e++) { sc[e] = expf(logits[e] - mx); se += sc[e]; }
        float inv = 1.f / se;
        for (int e = 0; e < NEXP; e++) sc[e] *= inv;

        int   idx[KSEL]; float w[KSEL]; float wsum = 0.f;
        bool used[NEXP];
        for (int e = 0; e < NEXP; e++) used[e] = false;
        for (int k = 0; k < KSEL; k++) {
            int best = 0; float bv = -1.f;
            for (int e = 0; e < NEXP; e++)
                if (!used[e] && sc[e] > bv) { bv = sc[e]; best = e; }
            used[best] = true; idx[k] = best; w[k] = bv; wsum += bv;
        }
        float iw = 1.f / wsum;
        for (int k = 0; k < KSEL; k++) {
            int e = idx[k];
            int pos = atomicAdd(&g_counts[e], 1);
            g_tokens[e * T_TOK + pos] = t;
            g_wts[e * T_TOK + pos]    = w[k] * iw;
        }
    }
}

// ---------------- kernel 2: gate/up GEMM + SwiGLU epilogue ----------------
// C-tile: 128 (rows = expert's gathered tokens) x 64 (intermediate cols).
// Computes BOTH g and u accumulators in one pass over K=H, then writes
// silu(g)*u*route_weight to the activation scratch.
__global__ __launch_bounds__(256, 2)
void up_gemm_kernel(const float* __restrict__ X,
                    const float* __restrict__ Wg, const float* __restrict__ Wu,
                    long wExpStride, int ldB, int routed)
{
    int e = blockIdx.z;
    int count = routed ? g_counts[e] : T_TOK;
    int m0 = blockIdx.y * 128;
    if (m0 >= count) return;
    int n0 = blockIdx.x * 64;
    const int Kdim = HDIM;

    const float* Bg = Wg + (size_t)e * wExpStride + n0;
    const float* Bu = Wu + (size_t)e * wExpStride + n0;
    const int* toks = routed ? (g_tokens + e * T_TOK) : nullptr;

    __shared__ __align__(16) float As[16][128];
    __shared__ __align__(16) float Sg[16][64];
    __shared__ __align__(16) float Su[16][64];

    int tid = threadIdx.x;
    int tx = tid & 15, ty = tid >> 4;

    // A-tile loader mapping: 128x16 floats = 512 float4; 2 per thread
    int arow0 = tid >> 2;
    int arow1 = arow0 + 64;
    int ac4   = (tid & 3) * 4;
    bool v0 = (m0 + arow0) < count;
    bool v1 = (m0 + arow1) < count;
    int tok0 = v0 ? (routed ? toks[m0 + arow0] : (m0 + arow0)) : 0;
    int tok1 = v1 ? (routed ? toks[m0 + arow1] : (m0 + arow1)) : 0;
    const float* xp0 = X + (size_t)tok0 * Kdim + ac4;
    const float* xp1 = X + (size_t)tok1 * Kdim + ac4;

    // B-tile loader mapping: 16x64 floats = 256 float4; 1 per thread (x2 matrices)
    int brow = tid >> 4;
    int bc4  = (tid & 15) * 4;
    const float* bgp = Bg + (size_t)brow * ldB + bc4;
    const float* bup = Bu + (size_t)brow * ldB + bc4;

    float accg[8][4], accu[8][4];
    #pragma unroll
    for (int i = 0; i < 8; i++)
        #pragma unroll
        for (int j = 0; j < 4; j++) { accg[i][j] = 0.f; accu[i][j] = 0.f; }

    for (int k0 = 0; k0 < Kdim; k0 += 16) {
        float4 a0  = v0 ? *(const float4*)(xp0 + k0) : make_float4(0.f, 0.f, 0.f, 0.f);
        float4 a1  = v1 ? *(const float4*)(xp1 + k0) : make_float4(0.f, 0.f, 0.f, 0.f);
        float4 bgv = *(const float4*)(bgp + (size_t)k0 * ldB);
        float4 buv = *(const float4*)(bup + (size_t)k0 * ldB);
        __syncthreads();
        As[ac4 + 0][arow0] = a0.x; As[ac4 + 1][arow0] = a0.y;
        As[ac4 + 2][arow0] = a0.z; As[ac4 + 3][arow0] = a0.w;
        As[ac4 + 0][arow1] = a1.x; As[ac4 + 1][arow1] = a1.y;
        As[ac4 + 2][arow1] = a1.z; As[ac4 + 3][arow1] = a1.w;
        *(float4*)&Sg[brow][bc4] = bgv;
        *(float4*)&Su[brow][bc4] = buv;
        __syncthreads();
        #pragma unroll
        for (int kk = 0; kk < 16; kk++) {
            float a[8], bg[4], bu[4];
            *(float4*)&a[0] = *(const float4*)&As[kk][ty * 8];
            *(float4*)&a[4] = *(const float4*)&As[kk][ty * 8 + 4];
            *(float4*)&bg[0] = *(const float4*)&Sg[kk][tx * 4];
            *(float4*)&bu[0] = *(const float4*)&Su[kk][tx * 4];
            #pragma unroll
            for (int i = 0; i < 8; i++)
                #pragma unroll
                for (int j = 0; j < 4; j++) {
                    accg[i][j] = fmaf(a[i], bg[j], accg[i][j]);
                    accu[i][j] = fmaf(a[i], bu[j], accu[i][j]);
                }
        }
    }

    float* actBase = routed ? (g_act + (size_t)e * T_TOK * IDIM) : g_acts;
    int actLd = routed ? IDIM : ISDIM;
    #pragma unroll
    for (int i = 0; i < 8; i++) {
        int m = m0 + ty * 8 + i;
        if (m >= count) continue;
        float w = routed ? g_wts[e * T_TOK + m] : 1.0f;
        float vals[4];
        #pragma unroll
        for (int j = 0; j < 4; j++) {
            float g = accg[i][j];
            float s = g / (1.f + expf(-g));   // silu
            vals[j] = s * accu[i][j] * w;
        }
        *(float4*)&actBase[(size_t)m * actLd + n0 + tx * 4] = *(float4*)vals;
    }
}

// ---------------- kernel 3: down-proj GEMM ----------------
// C-tile: 128 x 64 over H. Shared path: plain stores (fully covers out,
// launched first => no zero-init needed). Routed path: atomicAdd on top.
__global__ __launch_bounds__(256, 2)
void down_gemm_kernel(const float* __restrict__ Wd, long wExpStride,
                      float* __restrict__ out, int routed)
{
    int e = blockIdx.z;
    int count = routed ? g_counts[e] : T_TOK;
    int m0 = blockIdx.y * 128;
    if (m0 >= count) return;
    int n0 = blockIdx.x * 64;
    int Kdim = routed ? IDIM : ISDIM;

    const float* A = routed ? (g_act + (size_t)e * T_TOK * IDIM) : g_acts;
    int lda = Kdim;
    const float* B = Wd + (size_t)e * wExpStride + n0;   // row stride HDIM

    __shared__ __align__(16) float As[16][128];
    __shared__ __align__(16) float Bs[16][64];

    int tid = threadIdx.x;
    int tx = tid & 15, ty = tid >> 4;

    int arow0 = tid >> 2;
    int arow1 = arow0 + 64;
    int ac4   = (tid & 3) * 4;
    bool v0 = (m0 + arow0) < count;
    bool v1 = (m0 + arow1) < count;
    const float* ap0 = A + (size_t)(m0 + arow0) * lda + ac4;
    const float* ap1 = A + (size_t)(m0 + arow1) * lda + ac4;

    int brow = tid >> 4;
    int bc4  = (tid & 15) * 4;
    const float* bp = B + (size_t)brow * HDIM + bc4;

    float acc[8][4];
    #pragma unroll
    for (int i = 0; i < 8; i++)
        #pragma unroll
        for (int j = 0; j < 4; j++) acc[i][j] = 0.f;

    for (int k0 = 0; k0 < Kdim; k0 += 16) {
        float4 a0 = v0 ? *(const float4*)(ap0 + k0) : make_float4(0.f, 0.f, 0.f, 0.f);
        float4 a1 = v1 ? *(const float4*)(ap1 + k0) : make_float4(0.f, 0.f, 0.f, 0.f);
        float4 bv = *(const float4*)(bp + (size_t)k0 * HDIM);
        __syncthreads();
        As[ac4 + 0][arow0] = a0.x; As[ac4 + 1][arow0] = a0.y;
        As[ac4 + 2][arow0] = a0.z; As[ac4 + 3][arow0] = a0.w;
        As[ac4 + 0][arow1] = a1.x; As[ac4 + 1][arow1] = a1.y;
        As[ac4 + 2][arow1] = a1.z; As[ac4 + 3][arow1] = a1.w;
        *(float4*)&Bs[brow][bc4] = bv;
        __syncthreads();
        #pragma unroll
        for (int kk = 0; kk < 16; kk++) {
            float a[8], b[4];
            *(float4*)&a[0] = *(const float4*)&As[kk][ty * 8];
            *(float4*)&a[4] = *(const float4*)&As[kk][ty * 8 + 4];
            *(float4*)&b[0] = *(const float4*)&Bs[kk][tx * 4];
            #pragma unroll
            for (int i = 0; i < 8; i++)
                #pragma unroll
                for (int j = 0; j < 4; j++)
                    acc[i][j] = fmaf(a[i], b[j], acc[i][j]);
        }
    }

    const int* toks = routed ? (g_tokens + e * T_TOK) : nullptr;
    #pragma unroll
    for (int i = 0; i < 8; i++) {
        int m = m0 + ty * 8 + i;
        if (m >= count) continue;
        if (routed) {
            int t = toks[m];
            float* op = out + (size_t)t * HDIM + n0 + tx * 4;
            #pragma unroll
            for (int j = 0; j < 4; j++) atomicAdd(op + j, acc[i][j]);
        } else {
            float vals[4];
            #pragma unroll
            for (int j = 0; j < 4; j++) vals[j] = acc[i][j];
            *(float4*)(out + (size_t)m * HDIM + n0 + tx * 4) = *(float4*)vals;
        }
    }
}

// ---------------- launch ----------------
extern "C" void kernel_launch(void* const* d_in, const int* in_sizes, int n_in,
                              void* d_out, int out_size) {
    (void)in_sizes; (void)n_in; (void)out_size;
    const float* x       = (const float*)d_in[0];
    const float* gate_w  = (const float*)d_in[1];
    const float* w_gate  = (const float*)d_in[2];
    const float* w_up    = (const float*)d_in[3];
    const float* w_down  = (const float*)d_in[4];
    const float* sw_gate = (const float*)d_in[5];
    const float* sw_up   = (const float*)d_in[6];
    const float* sw_down = (const float*)d_in[7];
    float* out = (float*)d_out;

    zero_counts_kernel<<<1, 32>>>();
    gate_kernel<<<T_TOK, 256>>>(x, gate_w);

    // routed gate/up: grid (I/64, T/128, E) with early-exit past each expert's count
    dim3 g1r(IDIM / 64, T_TOK / 128, NEXP);
    up_gemm_kernel<<<g1r, 256>>>(x, w_gate, w_up, (long)HDIM * IDIM, IDIM, 1);

    // shared gate/up
    dim3 g1s(ISDIM / 64, T_TOK / 128, 1);
    up_gemm_kernel<<<g1s, 256>>>(x, sw_gate, sw_up, 0L, ISDIM, 0);

    // shared down-proj: plain stores, fully initializes out
    dim3 g2s(HDIM / 64, T_TOK / 128, 1);
    down_gemm_kernel<<<g2s, 256>>>(sw_down, 0L, out, 0);

    // routed down-proj: atomicAdd on top
    dim3 g2r(HDIM / 64, T_TOK / 128, NEXP);
    down_gemm_kernel<<<g2r, 256>>>(w_down, (long)IDIM * HDIM, out, 1);
}